// round 12
// baseline (speedup 1.0000x reference)
#include <cuda_runtime.h>
#include <cuda_bf16.h>

// CollisionRegularizer: mean over (B,N,N) of relu(R - dist)^2, diagonal masked.
// B=2, N=8192, xyz float32 (B,N,3). Output: 1 float (the mean).
//
// R8: persistent kernel, saturated. vs R7 (36.9us, issue 10.6%, occ 12.5%):
//  - 1024-thread blocks (32 warps/SM, occ 50%).
//  - Segment = warp; ranks/counts via __match_any_sync (O(1), no 255-iter scan).
//  - P2a warp-per-cell shfl-scan over 256 segment counts.
//  - Grid barrier: pure L2 spin (no nanosleep), monotonic phase base across
//    graph replays (no reset race).
// Deterministic: atomics only on integer counts/barrier words; every float
// accumulation in fixed order; scatter positions are pure functions of input.

#define RADIUS  0.1f
#define NPTS    8192
#define NBATCH  2
#define GRES    10
#define NCELLS  (GRES * GRES * GRES)          // 1000
#define NCELLT  (NBATCH * NCELLS)             // 2000
#define NSEGB   (NPTS / 32)                   // 256 warp-segments per batch
#define NSEGT   (NBATCH * NSEGB)              // 512
#define GRID    148
#define BT      1024
#define WPB     (BT / 32)                     // 32 warps per block
#define NWARP   (GRID * WPB)                  // 4736
#define CAP     64                            // staged own-points per cell

__device__ int   g_segcnt[NBATCH][NCELLS][NSEGB];  // [b][c][sg] counts
__device__ int   g_segoff[NBATCH][NCELLS][NSEGB];  // within-cell prefix
__device__ int   g_ctot[NBATCH][NCELLS];
__device__ int   g_start[NBATCH][NCELLS + 1];
__device__ float g_px[NBATCH][NPTS];
__device__ float g_py[NBATCH][NPTS];
__device__ float g_pz[NBATCH][NPTS];
__device__ float g_part[GRID];

__device__ unsigned int          g_arrive  = 0;   // monotonic across replays
__device__ volatile unsigned int g_release = 0;   // monotonic across replays

__device__ __forceinline__ float sqrt_approx(float x) {
    float r; asm("sqrt.approx.f32 %0, %1;" : "=f"(r) : "f"(x)); return r;
}
__device__ __forceinline__ float r_minus(float d, float R) {
    float r; asm("fma.rn.f32 %0, %1, 0fBF800000, %2;" : "=f"(r) : "f"(d), "f"(R)); return r;
}

// Grid barrier crossing number m = base + k (monotonic across graph replays).
__device__ __forceinline__ void grid_barrier(unsigned int m) {
    __syncthreads();
    if (threadIdx.x == 0) {
        __threadfence();
        const unsigned int t = atomicAdd(&g_arrive, 1u);
        if (t == m * GRID - 1u) {
            g_release = m;                 // release (fence above)
        } else {
            while (g_release < m) { }      // pure L2 spin
        }
        __threadfence();                   // acquire
    }
    __syncthreads();
}

__device__ __forceinline__ int point_cell(const float* __restrict__ p,
                                          float& x, float& y, float& z) {
    x = p[0]; y = p[1]; z = p[2];
    const int cx = min((int)(x * (float)GRES), GRES - 1);
    const int cy = min((int)(y * (float)GRES), GRES - 1);
    const int cz = min((int)(z * (float)GRES), GRES - 1);
    return cx + GRES * cy + GRES * GRES * cz;
}

__global__ __launch_bounds__(BT, 1)
void collreg_persistent(const float* __restrict__ xyz, float* __restrict__ out) {
    __shared__ union {
        int   scan[BT];
        struct { float wx[WPB][CAP]; float wy[WPB][CAP]; float wz[WPB][CAP];
                 float wred[WPB]; } p4;
        float fin[BT];
    } sm;

    const int tid  = threadIdx.x;
    const int blk  = blockIdx.x;
    const int lane = tid & 31;
    const int wid  = tid >> 5;
    const int gw   = blk * WPB + wid;          // global warp id

    // Phase base: completed crossings from previous replays (stable at entry:
    // nobody writes g_release until all 148 blocks have arrived at barrier 1,
    // i.e. after every block has read it).
    const unsigned int base = g_release;

    // ---- P1: per-warp-segment cell counts (match_any, order-independent) --
    if (gw < NSEGT) {
        const int b  = gw / NSEGB;
        const int sg = gw % NSEGB;
        const int n  = sg * 32 + lane;
        float x, y, z;
        const int c = point_cell(xyz + ((size_t)b * NPTS + n) * 3, x, y, z);
        const unsigned int match = __match_any_sync(0xFFFFFFFFu, c);
        if (lane == (__ffs(match) - 1))        // group leader
            g_segcnt[b][c][sg] = __popc(match);
    }
    grid_barrier(base + 1);

    // ---- P2a: warp per cell — shfl scan over 256 segment counts ----------
    if (gw < NCELLT) {
        const int b = gw / NCELLS, c = gw % NCELLS;
        int carry = 0;
#pragma unroll
        for (int ch = 0; ch < NSEGB / 32; ch++) {
            const int sg = ch * 32 + lane;
            const int v  = g_segcnt[b][c][sg];
            g_segcnt[b][c][sg] = 0;            // reset for next replay
            int incl = v;
#pragma unroll
            for (int o = 1; o < 32; o <<= 1) {
                const int t = __shfl_up_sync(0xFFFFFFFFu, incl, o);
                if (lane >= o) incl += t;
            }
            g_segoff[b][c][sg] = incl - v + carry;
            carry += __shfl_sync(0xFFFFFFFFu, incl, 31);
        }
        if (lane == 0) g_ctot[b][c] = carry;
    }
    grid_barrier(base + 2);

    // ---- P2b: cell scan (block 0) -----------------------------------------
    if (blk == 0) {
        for (int b = 0; b < NBATCH; b++) {
            const int v = (tid < NCELLS) ? g_ctot[b][tid] : 0;
            sm.scan[tid] = v;
            __syncthreads();
            for (int off = 1; off < BT; off <<= 1) {
                const int t = (tid >= off) ? sm.scan[tid - off] : 0;
                __syncthreads();
                sm.scan[tid] += t;
                __syncthreads();
            }
            if (tid < NCELLS) {
                g_start[b][tid] = sm.scan[tid] - v;
                if (tid == NCELLS - 1) g_start[b][NCELLS] = sm.scan[tid];
            }
            __syncthreads();
        }
    }
    grid_barrier(base + 3);

    // ---- P3: deterministic scatter (rank recomputed via match_any) --------
    if (gw < NSEGT) {
        const int b  = gw / NSEGB;
        const int sg = gw % NSEGB;
        const int n  = sg * 32 + lane;
        float x, y, z;
        const int c = point_cell(xyz + ((size_t)b * NPTS + n) * 3, x, y, z);
        const unsigned int match = __match_any_sync(0xFFFFFFFFu, c);
        const int rank = __popc(match & ((1u << lane) - 1u));
        const int pos  = g_start[b][c] + g_segoff[b][c][sg] + rank;
        g_px[b][pos] = x;
        g_py[b][pos] = y;
        g_pz[b][pos] = z;
    }
    grid_barrier(base + 4);

    // ---- P4: warp per cell, pair evaluation -------------------------------
    const float R = RADIUS;
    float wtot = 0.0f;
    for (int cell = gw; cell < NCELLT; cell += NWARP) {
        const int b = cell / NCELLS, c = cell % NCELLS;
        const int cx = c % GRES, cy = (c / GRES) % GRES, cz = c / (GRES * GRES);
        const int i0  = g_start[b][c];
        const int cnt = g_start[b][c + 1] - i0;
        const int scnt = min(cnt, CAP);

        for (int l = lane; l < scnt; l += 32) {
            sm.p4.wx[wid][l] = g_px[b][i0 + l];
            sm.p4.wy[wid][l] = g_py[b][i0 + l];
            sm.p4.wz[wid][l] = g_pz[b][i0 + l];
        }
        __syncwarp();

        // Lane r (< 9) holds bounds of x-run r of the 27-cell neighborhood.
        int s0 = 0, s1 = 0;
        if (lane < 9) {
            const int nz = cz + lane / 3 - 1;
            const int ny = cy + lane % 3 - 1;
            if (nz >= 0 && nz < GRES && ny >= 0 && ny < GRES) {
                const int cb = GRES * ny + GRES * GRES * nz;
                s0 = g_start[b][max(cx - 1, 0) + cb];
                s1 = g_start[b][min(cx + 1, GRES - 1) + cb + 1];
            }
        }

        float acc0 = 0.0f, acc1 = 0.0f;   // dual chains (break FMA latency)
#pragma unroll
        for (int r = 0; r < 9; r++) {
            const int rs0 = __shfl_sync(0xFFFFFFFFu, s0, r);
            const int rs1 = __shfl_sync(0xFFFFFFFFu, s1, r);
            for (int jj = rs0 + lane; jj < rs1; jj += 32) {
                const float jx = g_px[b][jj];
                const float jy = g_py[b][jj];
                const float jz = g_pz[b][jj];
                int ii = 0;
                for (; ii + 1 < scnt; ii += 2) {
                    const float dx0 = sm.p4.wx[wid][ii]     - jx;
                    const float dy0 = sm.p4.wy[wid][ii]     - jy;
                    const float dz0 = sm.p4.wz[wid][ii]     - jz;
                    const float dx1 = sm.p4.wx[wid][ii + 1] - jx;
                    const float dy1 = sm.p4.wy[wid][ii + 1] - jy;
                    const float dz1 = sm.p4.wz[wid][ii + 1] - jz;
                    float q0 = dx0 * dx0; q0 = fmaf(dy0, dy0, q0); q0 = fmaf(dz0, dz0, q0);
                    float q1 = dx1 * dx1; q1 = fmaf(dy1, dy1, q1); q1 = fmaf(dz1, dz1, q1);
                    const float t0 = fmaxf(r_minus(sqrt_approx(q0), R), 0.0f);
                    acc0 = fmaf(t0, t0, acc0);
                    const float t1 = fmaxf(r_minus(sqrt_approx(q1), R), 0.0f);
                    acc1 = fmaf(t1, t1, acc1);
                }
                if (ii < scnt) {
                    const float dx = sm.p4.wx[wid][ii] - jx;
                    const float dy = sm.p4.wy[wid][ii] - jy;
                    const float dz = sm.p4.wz[wid][ii] - jz;
                    float q = dx * dx; q = fmaf(dy, dy, q); q = fmaf(dz, dz, q);
                    const float t = fmaxf(r_minus(sqrt_approx(q), R), 0.0f);
                    acc0 = fmaf(t, t, acc0);
                }
                for (int ov = CAP; ov < cnt; ov++) {   // exact rare overflow
                    const float dx = g_px[b][i0 + ov] - jx;
                    const float dy = g_py[b][i0 + ov] - jy;
                    const float dz = g_pz[b][i0 + ov] - jz;
                    float q = dx * dx; q = fmaf(dy, dy, q); q = fmaf(dz, dz, q);
                    const float t = fmaxf(r_minus(sqrt_approx(q), R), 0.0f);
                    acc1 = fmaf(t, t, acc1);
                }
            }
        }
        float acc = acc0 + acc1;
#pragma unroll
        for (int off = 16; off > 0; off >>= 1)        // deterministic bfly
            acc += __shfl_xor_sync(0xFFFFFFFFu, acc, off);
        wtot += acc;
        __syncwarp();
    }

    if (lane == 0) sm.p4.wred[wid] = wtot;
    __syncthreads();
    if (tid == 0) {
        float v = 0.0f;
#pragma unroll
        for (int w = 0; w < WPB; w++) v += sm.p4.wred[w];   // fixed order
        g_part[blk] = v;
    }
    grid_barrier(base + 5);

    // ---- P5: final fixed-order reduction (block 0) ------------------------
    if (blk == 0) {
        sm.fin[tid] = (tid < GRID) ? g_part[tid] : 0.0f;
        __syncthreads();
#pragma unroll
        for (int s = BT / 2; s > 0; s >>= 1) {
            if (tid < s) sm.fin[tid] += sm.fin[tid + s];
            __syncthreads();
        }
        if (tid == 0) {
            const float diag = (float)(NBATCH * NPTS) * (RADIUS * RADIUS);
            out[0] = (sm.fin[0] - diag) /
                     ((float)NBATCH * (float)NPTS * (float)NPTS);
            // No barrier-state reset: phase base is monotonic across replays.
        }
    }
}

extern "C" void kernel_launch(void* const* d_in, const int* in_sizes, int n_in,
                              void* d_out, int out_size) {
    const float* xyz = (const float*)d_in[0];
    float* out = (float*)d_out;
    (void)in_sizes; (void)n_in; (void)out_size;

    collreg_persistent<<<GRID, BT>>>(xyz, out);
}

// round 13
// speedup vs baseline: 1.0014x; 1.0014x over previous
#include <cuda_runtime.h>
#include <cuda_bf16.h>

// CollisionRegularizer: mean over (B,N,N) of relu(R - dist)^2, diagonal masked.
// B=2, N=8192, xyz float32 (B,N,3). Output: 1 float (the mean).
//
// R8: persistent kernel, saturated. vs R7 (36.9us, issue 10.6%, occ 12.5%):
//  - 1024-thread blocks (32 warps/SM, occ 50%).
//  - Segment = warp; ranks/counts via __match_any_sync (O(1), no 255-iter scan).
//  - P2a warp-per-cell shfl-scan over 256 segment counts.
//  - Grid barrier: pure L2 spin (no nanosleep), monotonic phase base across
//    graph replays (no reset race).
// Deterministic: atomics only on integer counts/barrier words; every float
// accumulation in fixed order; scatter positions are pure functions of input.

#define RADIUS  0.1f
#define NPTS    8192
#define NBATCH  2
#define GRES    10
#define NCELLS  (GRES * GRES * GRES)          // 1000
#define NCELLT  (NBATCH * NCELLS)             // 2000
#define NSEGB   (NPTS / 32)                   // 256 warp-segments per batch
#define NSEGT   (NBATCH * NSEGB)              // 512
#define GRID    148
#define BT      1024
#define WPB     (BT / 32)                     // 32 warps per block
#define NWARP   (GRID * WPB)                  // 4736
#define CAP     64                            // staged own-points per cell

__device__ int   g_segcnt[NBATCH][NCELLS][NSEGB];  // [b][c][sg] counts
__device__ int   g_segoff[NBATCH][NCELLS][NSEGB];  // within-cell prefix
__device__ int   g_ctot[NBATCH][NCELLS];
__device__ int   g_start[NBATCH][NCELLS + 1];
__device__ float g_px[NBATCH][NPTS];
__device__ float g_py[NBATCH][NPTS];
__device__ float g_pz[NBATCH][NPTS];
__device__ float g_part[GRID];

__device__ unsigned int          g_arrive  = 0;   // monotonic across replays
__device__ volatile unsigned int g_release = 0;   // monotonic across replays

__device__ __forceinline__ float sqrt_approx(float x) {
    float r; asm("sqrt.approx.f32 %0, %1;" : "=f"(r) : "f"(x)); return r;
}
__device__ __forceinline__ float r_minus(float d, float R) {
    float r; asm("fma.rn.f32 %0, %1, 0fBF800000, %2;" : "=f"(r) : "f"(d), "f"(R)); return r;
}

// Grid barrier crossing number m = base + k (monotonic across graph replays).
__device__ __forceinline__ void grid_barrier(unsigned int m) {
    __syncthreads();
    if (threadIdx.x == 0) {
        __threadfence();
        const unsigned int t = atomicAdd(&g_arrive, 1u);
        if (t == m * GRID - 1u) {
            g_release = m;                 // release (fence above)
        } else {
            while (g_release < m) { }      // pure L2 spin
        }
        __threadfence();                   // acquire
    }
    __syncthreads();
}

__device__ __forceinline__ int point_cell(const float* __restrict__ p,
                                          float& x, float& y, float& z) {
    x = p[0]; y = p[1]; z = p[2];
    const int cx = min((int)(x * (float)GRES), GRES - 1);
    const int cy = min((int)(y * (float)GRES), GRES - 1);
    const int cz = min((int)(z * (float)GRES), GRES - 1);
    return cx + GRES * cy + GRES * GRES * cz;
}

__global__ __launch_bounds__(BT, 1)
void collreg_persistent(const float* __restrict__ xyz, float* __restrict__ out) {
    __shared__ union {
        int   scan[BT];
        struct { float wx[WPB][CAP]; float wy[WPB][CAP]; float wz[WPB][CAP];
                 float wred[WPB]; } p4;
        float fin[BT];
    } sm;

    const int tid  = threadIdx.x;
    const int blk  = blockIdx.x;
    const int lane = tid & 31;
    const int wid  = tid >> 5;
    const int gw   = blk * WPB + wid;          // global warp id

    // Phase base: completed crossings from previous replays (stable at entry:
    // nobody writes g_release until all 148 blocks have arrived at barrier 1,
    // i.e. after every block has read it).
    const unsigned int base = g_release;

    // ---- P1: per-warp-segment cell counts (match_any, order-independent) --
    if (gw < NSEGT) {
        const int b  = gw / NSEGB;
        const int sg = gw % NSEGB;
        const int n  = sg * 32 + lane;
        float x, y, z;
        const int c = point_cell(xyz + ((size_t)b * NPTS + n) * 3, x, y, z);
        const unsigned int match = __match_any_sync(0xFFFFFFFFu, c);
        if (lane == (__ffs(match) - 1))        // group leader
            g_segcnt[b][c][sg] = __popc(match);
    }
    grid_barrier(base + 1);

    // ---- P2a: warp per cell — shfl scan over 256 segment counts ----------
    if (gw < NCELLT) {
        const int b = gw / NCELLS, c = gw % NCELLS;
        int carry = 0;
#pragma unroll
        for (int ch = 0; ch < NSEGB / 32; ch++) {
            const int sg = ch * 32 + lane;
            const int v  = g_segcnt[b][c][sg];
            g_segcnt[b][c][sg] = 0;            // reset for next replay
            int incl = v;
#pragma unroll
            for (int o = 1; o < 32; o <<= 1) {
                const int t = __shfl_up_sync(0xFFFFFFFFu, incl, o);
                if (lane >= o) incl += t;
            }
            g_segoff[b][c][sg] = incl - v + carry;
            carry += __shfl_sync(0xFFFFFFFFu, incl, 31);
        }
        if (lane == 0) g_ctot[b][c] = carry;
    }
    grid_barrier(base + 2);

    // ---- P2b: cell scan (block 0) -----------------------------------------
    if (blk == 0) {
        for (int b = 0; b < NBATCH; b++) {
            const int v = (tid < NCELLS) ? g_ctot[b][tid] : 0;
            sm.scan[tid] = v;
            __syncthreads();
            for (int off = 1; off < BT; off <<= 1) {
                const int t = (tid >= off) ? sm.scan[tid - off] : 0;
                __syncthreads();
                sm.scan[tid] += t;
                __syncthreads();
            }
            if (tid < NCELLS) {
                g_start[b][tid] = sm.scan[tid] - v;
                if (tid == NCELLS - 1) g_start[b][NCELLS] = sm.scan[tid];
            }
            __syncthreads();
        }
    }
    grid_barrier(base + 3);

    // ---- P3: deterministic scatter (rank recomputed via match_any) --------
    if (gw < NSEGT) {
        const int b  = gw / NSEGB;
        const int sg = gw % NSEGB;
        const int n  = sg * 32 + lane;
        float x, y, z;
        const int c = point_cell(xyz + ((size_t)b * NPTS + n) * 3, x, y, z);
        const unsigned int match = __match_any_sync(0xFFFFFFFFu, c);
        const int rank = __popc(match & ((1u << lane) - 1u));
        const int pos  = g_start[b][c] + g_segoff[b][c][sg] + rank;
        g_px[b][pos] = x;
        g_py[b][pos] = y;
        g_pz[b][pos] = z;
    }
    grid_barrier(base + 4);

    // ---- P4: warp per cell, pair evaluation -------------------------------
    const float R = RADIUS;
    float wtot = 0.0f;
    for (int cell = gw; cell < NCELLT; cell += NWARP) {
        const int b = cell / NCELLS, c = cell % NCELLS;
        const int cx = c % GRES, cy = (c / GRES) % GRES, cz = c / (GRES * GRES);
        const int i0  = g_start[b][c];
        const int cnt = g_start[b][c + 1] - i0;
        const int scnt = min(cnt, CAP);

        for (int l = lane; l < scnt; l += 32) {
            sm.p4.wx[wid][l] = g_px[b][i0 + l];
            sm.p4.wy[wid][l] = g_py[b][i0 + l];
            sm.p4.wz[wid][l] = g_pz[b][i0 + l];
        }
        __syncwarp();

        // Lane r (< 9) holds bounds of x-run r of the 27-cell neighborhood.
        int s0 = 0, s1 = 0;
        if (lane < 9) {
            const int nz = cz + lane / 3 - 1;
            const int ny = cy + lane % 3 - 1;
            if (nz >= 0 && nz < GRES && ny >= 0 && ny < GRES) {
                const int cb = GRES * ny + GRES * GRES * nz;
                s0 = g_start[b][max(cx - 1, 0) + cb];
                s1 = g_start[b][min(cx + 1, GRES - 1) + cb + 1];
            }
        }

        float acc0 = 0.0f, acc1 = 0.0f;   // dual chains (break FMA latency)
#pragma unroll
        for (int r = 0; r < 9; r++) {
            const int rs0 = __shfl_sync(0xFFFFFFFFu, s0, r);
            const int rs1 = __shfl_sync(0xFFFFFFFFu, s1, r);
            for (int jj = rs0 + lane; jj < rs1; jj += 32) {
                const float jx = g_px[b][jj];
                const float jy = g_py[b][jj];
                const float jz = g_pz[b][jj];
                int ii = 0;
                for (; ii + 1 < scnt; ii += 2) {
                    const float dx0 = sm.p4.wx[wid][ii]     - jx;
                    const float dy0 = sm.p4.wy[wid][ii]     - jy;
                    const float dz0 = sm.p4.wz[wid][ii]     - jz;
                    const float dx1 = sm.p4.wx[wid][ii + 1] - jx;
                    const float dy1 = sm.p4.wy[wid][ii + 1] - jy;
                    const float dz1 = sm.p4.wz[wid][ii + 1] - jz;
                    float q0 = dx0 * dx0; q0 = fmaf(dy0, dy0, q0); q0 = fmaf(dz0, dz0, q0);
                    float q1 = dx1 * dx1; q1 = fmaf(dy1, dy1, q1); q1 = fmaf(dz1, dz1, q1);
                    const float t0 = fmaxf(r_minus(sqrt_approx(q0), R), 0.0f);
                    acc0 = fmaf(t0, t0, acc0);
                    const float t1 = fmaxf(r_minus(sqrt_approx(q1), R), 0.0f);
                    acc1 = fmaf(t1, t1, acc1);
                }
                if (ii < scnt) {
                    const float dx = sm.p4.wx[wid][ii] - jx;
                    const float dy = sm.p4.wy[wid][ii] - jy;
                    const float dz = sm.p4.wz[wid][ii] - jz;
                    float q = dx * dx; q = fmaf(dy, dy, q); q = fmaf(dz, dz, q);
                    const float t = fmaxf(r_minus(sqrt_approx(q), R), 0.0f);
                    acc0 = fmaf(t, t, acc0);
                }
                for (int ov = CAP; ov < cnt; ov++) {   // exact rare overflow
                    const float dx = g_px[b][i0 + ov] - jx;
                    const float dy = g_py[b][i0 + ov] - jy;
                    const float dz = g_pz[b][i0 + ov] - jz;
                    float q = dx * dx; q = fmaf(dy, dy, q); q = fmaf(dz, dz, q);
                    const float t = fmaxf(r_minus(sqrt_approx(q), R), 0.0f);
                    acc1 = fmaf(t, t, acc1);
                }
            }
        }
        float acc = acc0 + acc1;
#pragma unroll
        for (int off = 16; off > 0; off >>= 1)        // deterministic bfly
            acc += __shfl_xor_sync(0xFFFFFFFFu, acc, off);
        wtot += acc;
        __syncwarp();
    }

    if (lane == 0) sm.p4.wred[wid] = wtot;
    __syncthreads();
    if (tid == 0) {
        float v = 0.0f;
#pragma unroll
        for (int w = 0; w < WPB; w++) v += sm.p4.wred[w];   // fixed order
        g_part[blk] = v;
    }
    grid_barrier(base + 5);

    // ---- P5: final fixed-order reduction (block 0) ------------------------
    if (blk == 0) {
        sm.fin[tid] = (tid < GRID) ? g_part[tid] : 0.0f;
        __syncthreads();
#pragma unroll
        for (int s = BT / 2; s > 0; s >>= 1) {
            if (tid < s) sm.fin[tid] += sm.fin[tid + s];
            __syncthreads();
        }
        if (tid == 0) {
            const float diag = (float)(NBATCH * NPTS) * (RADIUS * RADIUS);
            out[0] = (sm.fin[0] - diag) /
                     ((float)NBATCH * (float)NPTS * (float)NPTS);
            // No barrier-state reset: phase base is monotonic across replays.
        }
    }
}

extern "C" void kernel_launch(void* const* d_in, const int* in_sizes, int n_in,
                              void* d_out, int out_size) {
    const float* xyz = (const float*)d_in[0];
    float* out = (float*)d_out;
    (void)in_sizes; (void)n_in; (void)out_size;

    collreg_persistent<<<GRID, BT>>>(xyz, out);
}

// round 14
// speedup vs baseline: 1.3539x; 1.3520x over previous
#include <cuda_runtime.h>
#include <cuda_bf16.h>

// CollisionRegularizer: mean over (B,N,N) of relu(R - dist)^2, diagonal masked.
// B=2, N=8192, xyz float32 (B,N,3). Output: 1 float (the mean).
//
// R9: binned pipeline as FOUR lean kernels (persistent/grid-barrier approach
// abandoned — barriers cost more than in-graph launches). No single-block
// islands: the two serial steps (cell scan, final reduce) run as last-block
// tickets fused into parallel kernels.
//  K1: per-warp-segment cell counts (__match_any_sync, order-independent).
//  K2: warp-per-cell shfl scan of segment counts (+zero for replay);
//      last block does the 1000-cell 3-level scan.
//  K3: deterministic scatter (rank via match_any; no atomics).
//  K4: warp-per-cell pair evaluation + fused last-block final reduction.
// Deterministic: atomics only on integer counts/tickets; all float sums in
// fixed order; scatter positions are pure functions of the input.

#define RADIUS  0.1f
#define NPTS    8192
#define NBATCH  2
#define GRES    10
#define NCELLS  (GRES * GRES * GRES)          // 1000
#define NCELLT  (NBATCH * NCELLS)             // 2000
#define NSEGB   (NPTS / 32)                   // 256 warp-segments per batch
#define NSEGT   (NBATCH * NSEGB)              // 512
#define CAP     64                            // staged own-points per cell

#define T256    256
#define B1      (NSEGT / 8)                   // 64 blocks  (8 warps each)
#define B2      (NCELLT / 8)                  // 250 blocks
#define B3      (NSEGT / 8)                   // 64 blocks
#define B4      (NCELLT / 8)                  // 250 blocks

__device__ int   g_segcnt[NBATCH][NCELLS][NSEGB];
__device__ int   g_segoff[NBATCH][NCELLS][NSEGB];
__device__ int   g_ctot[NBATCH][NCELLS];
__device__ int   g_start[NBATCH][NCELLS + 1];
__device__ float g_px[NBATCH][NPTS];
__device__ float g_py[NBATCH][NPTS];
__device__ float g_pz[NBATCH][NPTS];
__device__ float g_part[B4];
__device__ unsigned int g_tick2 = 0;
__device__ unsigned int g_tick4 = 0;

__device__ __forceinline__ float sqrt_approx(float x) {
    float r; asm("sqrt.approx.f32 %0, %1;" : "=f"(r) : "f"(x)); return r;
}
__device__ __forceinline__ float r_minus(float d, float R) {
    float r; asm("fma.rn.f32 %0, %1, 0fBF800000, %2;" : "=f"(r) : "f"(d), "f"(R)); return r;
}
__device__ __forceinline__ int point_cell(const float* __restrict__ p,
                                          float& x, float& y, float& z) {
    x = p[0]; y = p[1]; z = p[2];
    const int cx = min((int)(x * (float)GRES), GRES - 1);
    const int cy = min((int)(y * (float)GRES), GRES - 1);
    const int cz = min((int)(z * (float)GRES), GRES - 1);
    return cx + GRES * cy + GRES * GRES * cz;
}

// ---- K1: per-warp-segment cell counts -----------------------------------
__global__ __launch_bounds__(T256)
void k1_count(const float* __restrict__ xyz) {
    const int lane = threadIdx.x & 31;
    const int gw   = blockIdx.x * 8 + (threadIdx.x >> 5);   // 0..511
    const int b  = gw / NSEGB;
    const int sg = gw % NSEGB;
    const int n  = sg * 32 + lane;
    float x, y, z;
    const int c = point_cell(xyz + ((size_t)b * NPTS + n) * 3, x, y, z);
    const unsigned int match = __match_any_sync(0xFFFFFFFFu, c);
    if (lane == (__ffs(match) - 1))
        g_segcnt[b][c][sg] = __popc(match);
}

// ---- K2: per-cell segment scan + last-block cell scan -------------------
__global__ __launch_bounds__(T256)
void k2_scan() {
    __shared__ int  swarp[8];
    __shared__ bool is_last;
    const int tid  = threadIdx.x;
    const int lane = tid & 31;
    const int wid  = tid >> 5;
    const int gw   = blockIdx.x * 8 + wid;    // 0..1999 (= NCELLT exactly)

    {   // warp-per-cell: exclusive scan over 256 segment counts
        const int b = gw / NCELLS, c = gw % NCELLS;
        int carry = 0;
#pragma unroll
        for (int ch = 0; ch < NSEGB / 32; ch++) {
            const int sg = ch * 32 + lane;
            const int v  = g_segcnt[b][c][sg];
            g_segcnt[b][c][sg] = 0;           // reset for next graph replay
            int incl = v;
#pragma unroll
            for (int o = 1; o < 32; o <<= 1) {
                const int t = __shfl_up_sync(0xFFFFFFFFu, incl, o);
                if (lane >= o) incl += t;
            }
            g_segoff[b][c][sg] = incl - v + carry;
            carry += __shfl_sync(0xFFFFFFFFu, incl, 31);
        }
        if (lane == 0) g_ctot[b][c] = carry;
    }

    // last-block ticket -> 1000-cell exclusive scan per batch
    __syncthreads();
    if (tid == 0) {
        __threadfence();
        is_last = (atomicAdd(&g_tick2, 1u) == B2 - 1u);
        if (is_last) g_tick2 = 0;             // reset for next replay
    }
    __syncthreads();
    if (!is_last) return;
    __threadfence();

    for (int b = 0; b < NBATCH; b++) {
        const int i0 = tid * 4;               // 256 threads x 4 cells = 1024
        int v0 = (i0 + 0 < NCELLS) ? g_ctot[b][i0 + 0] : 0;
        int v1 = (i0 + 1 < NCELLS) ? g_ctot[b][i0 + 1] : 0;
        int v2 = (i0 + 2 < NCELLS) ? g_ctot[b][i0 + 2] : 0;
        int v3 = (i0 + 3 < NCELLS) ? g_ctot[b][i0 + 3] : 0;
        const int s = v0 + v1 + v2 + v3;
        int incl = s;
#pragma unroll
        for (int o = 1; o < 32; o <<= 1) {
            const int t = __shfl_up_sync(0xFFFFFFFFu, incl, o);
            if (lane >= o) incl += t;
        }
        if (lane == 31) swarp[wid] = incl;
        __syncthreads();
        if (wid == 0 && lane < 8) {
            int wv = swarp[lane], wincl = wv;
#pragma unroll
            for (int o = 1; o < 8; o <<= 1) {
                const int t = __shfl_up_sync(0xFFu, wincl, o);
                if (lane >= o) wincl += t;
            }
            swarp[lane] = wincl - wv;         // exclusive warp offset
        }
        __syncthreads();
        const int excl = incl - s + swarp[wid];
        if (i0 + 0 < NCELLS) g_start[b][i0 + 0] = excl;
        if (i0 + 1 < NCELLS) g_start[b][i0 + 1] = excl + v0;
        if (i0 + 2 < NCELLS) g_start[b][i0 + 2] = excl + v0 + v1;
        if (i0 + 3 < NCELLS) g_start[b][i0 + 3] = excl + v0 + v1 + v2;
        if (i0 + 4 == NCELLS) g_start[b][NCELLS] = excl + s;
        __syncthreads();
    }
}

// ---- K3: deterministic scatter ------------------------------------------
__global__ __launch_bounds__(T256)
void k3_scatter(const float* __restrict__ xyz) {
    const int lane = threadIdx.x & 31;
    const int gw   = blockIdx.x * 8 + (threadIdx.x >> 5);
    const int b  = gw / NSEGB;
    const int sg = gw % NSEGB;
    const int n  = sg * 32 + lane;
    float x, y, z;
    const int c = point_cell(xyz + ((size_t)b * NPTS + n) * 3, x, y, z);
    const unsigned int match = __match_any_sync(0xFFFFFFFFu, c);
    const int rank = __popc(match & ((1u << lane) - 1u));
    const int pos  = g_start[b][c] + g_segoff[b][c][sg] + rank;
    g_px[b][pos] = x;
    g_py[b][pos] = y;
    g_pz[b][pos] = z;
}

// ---- K4: warp-per-cell evaluation + fused final reduction ---------------
__global__ __launch_bounds__(T256)
void k4_main(float* __restrict__ out) {
    __shared__ __align__(16) float wx[8][CAP];
    __shared__ __align__(16) float wy[8][CAP];
    __shared__ __align__(16) float wz[8][CAP];
    __shared__ float sred[T256];
    __shared__ bool  is_last;

    const int tid  = threadIdx.x;
    const int lane = tid & 31;
    const int wid  = tid >> 5;
    const int cell = blockIdx.x * 8 + wid;    // exactly one cell per warp
    const int b = cell / NCELLS, c = cell % NCELLS;
    const int cx = c % GRES, cy = (c / GRES) % GRES, cz = c / (GRES * GRES);

    const int i0  = g_start[b][c];
    const int cnt = g_start[b][c + 1] - i0;
    const int scnt = min(cnt, CAP);

    for (int l = lane; l < scnt; l += 32) {
        wx[wid][l] = g_px[b][i0 + l];
        wy[wid][l] = g_py[b][i0 + l];
        wz[wid][l] = g_pz[b][i0 + l];
    }
    __syncwarp();

    // Lane r (<9) holds the bounds of x-run r of the 27-cell neighborhood.
    int s0 = 0, s1 = 0;
    if (lane < 9) {
        const int nz = cz + lane / 3 - 1;
        const int ny = cy + lane % 3 - 1;
        if (nz >= 0 && nz < GRES && ny >= 0 && ny < GRES) {
            const int cb = GRES * ny + GRES * GRES * nz;
            s0 = g_start[b][max(cx - 1, 0) + cb];
            s1 = g_start[b][min(cx + 1, GRES - 1) + cb + 1];
        }
    }

    const float R = RADIUS;
    float acc0 = 0.0f, acc1 = 0.0f;
#pragma unroll
    for (int r = 0; r < 9; r++) {
        const int rs0 = __shfl_sync(0xFFFFFFFFu, s0, r);
        const int rs1 = __shfl_sync(0xFFFFFFFFu, s1, r);
        for (int jj = rs0 + lane; jj < rs1; jj += 32) {
            const float jx = g_px[b][jj];
            const float jy = g_py[b][jj];
            const float jz = g_pz[b][jj];
            int ii = 0;
            for (; ii + 1 < scnt; ii += 2) {
                const float dx0 = wx[wid][ii]     - jx;
                const float dy0 = wy[wid][ii]     - jy;
                const float dz0 = wz[wid][ii]     - jz;
                const float dx1 = wx[wid][ii + 1] - jx;
                const float dy1 = wy[wid][ii + 1] - jy;
                const float dz1 = wz[wid][ii + 1] - jz;
                float q0 = dx0 * dx0; q0 = fmaf(dy0, dy0, q0); q0 = fmaf(dz0, dz0, q0);
                float q1 = dx1 * dx1; q1 = fmaf(dy1, dy1, q1); q1 = fmaf(dz1, dz1, q1);
                const float t0 = fmaxf(r_minus(sqrt_approx(q0), R), 0.0f);
                acc0 = fmaf(t0, t0, acc0);
                const float t1 = fmaxf(r_minus(sqrt_approx(q1), R), 0.0f);
                acc1 = fmaf(t1, t1, acc1);
            }
            if (ii < scnt) {
                const float dx = wx[wid][ii] - jx;
                const float dy = wy[wid][ii] - jy;
                const float dz = wz[wid][ii] - jz;
                float q = dx * dx; q = fmaf(dy, dy, q); q = fmaf(dz, dz, q);
                const float t = fmaxf(r_minus(sqrt_approx(q), R), 0.0f);
                acc0 = fmaf(t, t, acc0);
            }
            for (int ov = CAP; ov < cnt; ov++) {   // exact, astronomically rare
                const float dx = g_px[b][i0 + ov] - jx;
                const float dy = g_py[b][i0 + ov] - jy;
                const float dz = g_pz[b][i0 + ov] - jz;
                float q = dx * dx; q = fmaf(dy, dy, q); q = fmaf(dz, dz, q);
                const float t = fmaxf(r_minus(sqrt_approx(q), R), 0.0f);
                acc1 = fmaf(t, t, acc1);
            }
        }
    }
    float acc = acc0 + acc1;
#pragma unroll
    for (int off = 16; off > 0; off >>= 1)
        acc += __shfl_xor_sync(0xFFFFFFFFu, acc, off);

    if (lane == 0) sred[wid] = acc;
    __syncthreads();
    if (tid == 0) {
        float v = 0.0f;
#pragma unroll
        for (int w = 0; w < 8; w++) v += sred[w];   // fixed order
        g_part[blockIdx.x] = v;
        __threadfence();
        is_last = (atomicAdd(&g_tick4, 1u) == B4 - 1u);
        if (is_last) g_tick4 = 0;                   // reset for next replay
    }
    __syncthreads();

    if (is_last) {
        __threadfence();
        const volatile float* gp = g_part;
        sred[tid] = (tid < B4) ? gp[tid] : 0.0f;
        __syncthreads();
#pragma unroll
        for (int s = T256 / 2; s > 0; s >>= 1) {
            if (tid < s) sred[tid] += sred[tid + s];
            __syncthreads();
        }
        if (tid == 0) {
            // Self-pairs contributed exactly R^2 each (sqrt.approx(0)=0).
            const float diag = (float)(NBATCH * NPTS) * (RADIUS * RADIUS);
            out[0] = (sred[0] - diag) /
                     ((float)NBATCH * (float)NPTS * (float)NPTS);
        }
    }
}

extern "C" void kernel_launch(void* const* d_in, const int* in_sizes, int n_in,
                              void* d_out, int out_size) {
    const float* xyz = (const float*)d_in[0];
    float* out = (float*)d_out;
    (void)in_sizes; (void)n_in; (void)out_size;

    k1_count  <<<B1, T256>>>(xyz);
    k2_scan   <<<B2, T256>>>();
    k3_scatter<<<B3, T256>>>(xyz);
    k4_main   <<<B4, T256>>>(out);
}

// round 15
// speedup vs baseline: 1.7771x; 1.3126x over previous
#include <cuda_runtime.h>
#include <cuda_bf16.h>

// CollisionRegularizer: mean over (B,N,N) of relu(R - dist)^2, diagonal masked.
// B=2, N=8192, xyz float32 (B,N,3). Output: 1 float (the mean).
//
// R10 vs R9 (33.7us; K4=17us, prep=16.7us):
//  - K4 half-neighborhood: own cell (weight 1) + 13 forward cells as 5
//    x-runs (weight 2). Pair evals 7.3M -> 3.8M. Exact same sum, fixed order.
//  - g_segcnt -> uchar (counts <= 32 by construction), g_segoff -> ushort:
//    K2 traffic 6MB -> 2MB, uchar4-vectorized scan.
// Deterministic: atomics only on integer tickets; float sums in fixed order;
// scatter positions are pure functions of the input.

#define RADIUS  0.1f
#define NPTS    8192
#define NBATCH  2
#define GRES    10
#define NCELLS  (GRES * GRES * GRES)          // 1000
#define NCELLT  (NBATCH * NCELLS)             // 2000
#define NSEGB   (NPTS / 32)                   // 256 warp-segments per batch
#define NSEGT   (NBATCH * NSEGB)              // 512
#define CAP     64                            // staged own-points per cell

#define T256    256
#define B1      (NSEGT / 8)                   // 64 blocks
#define B2      (NCELLT / 8)                  // 250 blocks
#define B4      (NCELLT / 8)                  // 250 blocks

__device__ unsigned char  g_segcnt[NBATCH][NCELLS][NSEGB];   // <=32 each
__device__ unsigned short g_segoff[NBATCH][NCELLS][NSEGB];   // <= cell count
__device__ int   g_ctot[NBATCH][NCELLS];
__device__ int   g_start[NBATCH][NCELLS + 1];
__device__ float g_px[NBATCH][NPTS];
__device__ float g_py[NBATCH][NPTS];
__device__ float g_pz[NBATCH][NPTS];
__device__ float g_part[B4];
__device__ unsigned int g_tick2 = 0;
__device__ unsigned int g_tick4 = 0;

__device__ __forceinline__ float sqrt_approx(float x) {
    float r; asm("sqrt.approx.f32 %0, %1;" : "=f"(r) : "f"(x)); return r;
}
__device__ __forceinline__ float r_minus(float d, float R) {
    float r; asm("fma.rn.f32 %0, %1, 0fBF800000, %2;" : "=f"(r) : "f"(d), "f"(R)); return r;
}
__device__ __forceinline__ int point_cell(const float* __restrict__ p,
                                          float& x, float& y, float& z) {
    x = p[0]; y = p[1]; z = p[2];
    const int cx = min((int)(x * (float)GRES), GRES - 1);
    const int cy = min((int)(y * (float)GRES), GRES - 1);
    const int cz = min((int)(z * (float)GRES), GRES - 1);
    return cx + GRES * cy + GRES * GRES * cz;
}

// ---- K1: per-warp-segment cell counts (order-independent) ---------------
__global__ __launch_bounds__(T256)
void k1_count(const float* __restrict__ xyz) {
    const int lane = threadIdx.x & 31;
    const int gw   = blockIdx.x * 8 + (threadIdx.x >> 5);
    const int b  = gw / NSEGB;
    const int sg = gw % NSEGB;
    const int n  = sg * 32 + lane;
    float x, y, z;
    const int c = point_cell(xyz + ((size_t)b * NPTS + n) * 3, x, y, z);
    const unsigned int match = __match_any_sync(0xFFFFFFFFu, c);
    if (lane == (__ffs(match) - 1))
        g_segcnt[b][c][sg] = (unsigned char)__popc(match);
}

// ---- K2: per-cell segment scan (uchar4) + last-block cell scan ----------
__global__ __launch_bounds__(T256)
void k2_scan() {
    __shared__ int  swarp[8];
    __shared__ bool is_last;
    const int tid  = threadIdx.x;
    const int lane = tid & 31;
    const int wid  = tid >> 5;
    const int gw   = blockIdx.x * 8 + wid;    // 0..1999 == NCELLT

    {   // warp-per-cell: exclusive scan over 256 segment counts (as uchar4)
        const int b = gw / NCELLS, c = gw % NCELLS;
        uchar4*  cnt4 = reinterpret_cast<uchar4*>(&g_segcnt[b][c][0]);
        ushort4* off4 = reinterpret_cast<ushort4*>(&g_segoff[b][c][0]);
        int carry = 0;
#pragma unroll
        for (int ch = 0; ch < 2; ch++) {       // 2 x 32 lanes x 4 segs = 256
            const int w = ch * 32 + lane;
            const uchar4 v = cnt4[w];
            cnt4[w] = make_uchar4(0, 0, 0, 0); // reset for next replay
            const int s = v.x + v.y + v.z + v.w;
            int incl = s;
#pragma unroll
            for (int o = 1; o < 32; o <<= 1) {
                const int t = __shfl_up_sync(0xFFFFFFFFu, incl, o);
                if (lane >= o) incl += t;
            }
            const int e = incl - s + carry;
            off4[w] = make_ushort4((unsigned short)e,
                                   (unsigned short)(e + v.x),
                                   (unsigned short)(e + v.x + v.y),
                                   (unsigned short)(e + v.x + v.y + v.z));
            carry += __shfl_sync(0xFFFFFFFFu, incl, 31);
        }
        if (lane == 0) g_ctot[b][c] = carry;
    }

    __syncthreads();
    if (tid == 0) {
        __threadfence();
        is_last = (atomicAdd(&g_tick2, 1u) == B2 - 1u);
        if (is_last) g_tick2 = 0;
    }
    __syncthreads();
    if (!is_last) return;
    __threadfence();

    for (int b = 0; b < NBATCH; b++) {        // 1000-cell exclusive scan
        const int i0 = tid * 4;
        int v0 = (i0 + 0 < NCELLS) ? g_ctot[b][i0 + 0] : 0;
        int v1 = (i0 + 1 < NCELLS) ? g_ctot[b][i0 + 1] : 0;
        int v2 = (i0 + 2 < NCELLS) ? g_ctot[b][i0 + 2] : 0;
        int v3 = (i0 + 3 < NCELLS) ? g_ctot[b][i0 + 3] : 0;
        const int s = v0 + v1 + v2 + v3;
        int incl = s;
#pragma unroll
        for (int o = 1; o < 32; o <<= 1) {
            const int t = __shfl_up_sync(0xFFFFFFFFu, incl, o);
            if (lane >= o) incl += t;
        }
        if (lane == 31) swarp[wid] = incl;
        __syncthreads();
        if (wid == 0 && lane < 8) {
            int wv = swarp[lane], wincl = wv;
#pragma unroll
            for (int o = 1; o < 8; o <<= 1) {
                const int t = __shfl_up_sync(0xFFu, wincl, o);
                if (lane >= o) wincl += t;
            }
            swarp[lane] = wincl - wv;
        }
        __syncthreads();
        const int excl = incl - s + swarp[wid];
        if (i0 + 0 < NCELLS) g_start[b][i0 + 0] = excl;
        if (i0 + 1 < NCELLS) g_start[b][i0 + 1] = excl + v0;
        if (i0 + 2 < NCELLS) g_start[b][i0 + 2] = excl + v0 + v1;
        if (i0 + 3 < NCELLS) g_start[b][i0 + 3] = excl + v0 + v1 + v2;
        if (i0 + 4 == NCELLS) g_start[b][NCELLS] = excl + s;
        __syncthreads();
    }
}

// ---- K3: deterministic scatter ------------------------------------------
__global__ __launch_bounds__(T256)
void k3_scatter(const float* __restrict__ xyz) {
    const int lane = threadIdx.x & 31;
    const int gw   = blockIdx.x * 8 + (threadIdx.x >> 5);
    const int b  = gw / NSEGB;
    const int sg = gw % NSEGB;
    const int n  = sg * 32 + lane;
    float x, y, z;
    const int c = point_cell(xyz + ((size_t)b * NPTS + n) * 3, x, y, z);
    const unsigned int match = __match_any_sync(0xFFFFFFFFu, c);
    const int rank = __popc(match & ((1u << lane) - 1u));
    const int pos  = g_start[b][c] + (int)g_segoff[b][c][sg] + rank;
    g_px[b][pos] = x;
    g_py[b][pos] = y;
    g_pz[b][pos] = z;
}

// ---- K4: warp-per-cell, half-neighborhood, fused final reduction --------
__global__ __launch_bounds__(T256)
void k4_main(float* __restrict__ out) {
    __shared__ __align__(16) float wx[8][CAP];
    __shared__ __align__(16) float wy[8][CAP];
    __shared__ __align__(16) float wz[8][CAP];
    __shared__ float sred[T256];
    __shared__ bool  is_last;

    const int tid  = threadIdx.x;
    const int lane = tid & 31;
    const int wid  = tid >> 5;
    const int cell = blockIdx.x * 8 + wid;
    const int b = cell / NCELLS, c = cell % NCELLS;
    const int cx = c % GRES, cy = (c / GRES) % GRES, cz = c / (GRES * GRES);

    const int i0  = g_start[b][c];
    const int cnt = g_start[b][c + 1] - i0;
    const int scnt = min(cnt, CAP);

    for (int l = lane; l < scnt; l += 32) {
        wx[wid][l] = g_px[b][i0 + l];
        wy[wid][l] = g_py[b][i0 + l];
        wz[wid][l] = g_pz[b][i0 + l];
    }
    __syncwarp();

    // Forward half-neighborhood (13 cells) as 5 x-runs; lane r holds run r:
    //  r=0..2: dz=+1, dy=r-1, x in [cx-1,cx+1]
    //  r=3:    dz=0,  dy=+1,  x in [cx-1,cx+1]
    //  r=4:    dz=0,  dy=0,   x = cx+1
    int s0 = 0, s1 = 0;
    if (lane < 5) {
        int dy, dz, x0, x1;
        if (lane < 3)      { dz = 1; dy = lane - 1; x0 = max(cx - 1, 0); x1 = min(cx + 1, GRES - 1); }
        else if (lane == 3){ dz = 0; dy = 1;        x0 = max(cx - 1, 0); x1 = min(cx + 1, GRES - 1); }
        else               { dz = 0; dy = 0;        x0 = cx + 1;         x1 = cx + 1; }
        const int ny = cy + dy, nz = cz + dz;
        if (ny >= 0 && ny < GRES && nz >= 0 && nz < GRES && x0 < GRES && x1 < GRES) {
            const int cb = GRES * ny + GRES * GRES * nz;
            s0 = g_start[b][x0 + cb];
            s1 = g_start[b][x1 + cb + 1];
        }
    }

    const float R = RADIUS;
    float own0 = 0.0f, own1 = 0.0f, fwd0 = 0.0f, fwd1 = 0.0f;

#define PAIR_BODY(A0, A1, RS0, RS1)                                          \
    for (int jj = (RS0) + lane; jj < (RS1); jj += 32) {                      \
        const float jx = g_px[b][jj];                                        \
        const float jy = g_py[b][jj];                                        \
        const float jz = g_pz[b][jj];                                        \
        int ii = 0;                                                          \
        for (; ii + 1 < scnt; ii += 2) {                                     \
            const float dx0 = wx[wid][ii]     - jx;                          \
            const float dy0 = wy[wid][ii]     - jy;                          \
            const float dz0 = wz[wid][ii]     - jz;                          \
            const float dx1 = wx[wid][ii + 1] - jx;                          \
            const float dy1 = wy[wid][ii + 1] - jy;                          \
            const float dz1 = wz[wid][ii + 1] - jz;                          \
            float q0 = dx0 * dx0; q0 = fmaf(dy0, dy0, q0); q0 = fmaf(dz0, dz0, q0); \
            float q1 = dx1 * dx1; q1 = fmaf(dy1, dy1, q1); q1 = fmaf(dz1, dz1, q1); \
            const float t0 = fmaxf(r_minus(sqrt_approx(q0), R), 0.0f);       \
            A0 = fmaf(t0, t0, A0);                                           \
            const float t1 = fmaxf(r_minus(sqrt_approx(q1), R), 0.0f);       \
            A1 = fmaf(t1, t1, A1);                                           \
        }                                                                    \
        if (ii < scnt) {                                                     \
            const float dx = wx[wid][ii] - jx;                               \
            const float dy = wy[wid][ii] - jy;                               \
            const float dz = wz[wid][ii] - jz;                               \
            float q = dx * dx; q = fmaf(dy, dy, q); q = fmaf(dz, dz, q);     \
            const float t = fmaxf(r_minus(sqrt_approx(q), R), 0.0f);         \
            A0 = fmaf(t, t, A0);                                             \
        }                                                                    \
        for (int ov = CAP; ov < cnt; ov++) {  /* exact, astronomically rare */ \
            const float dx = g_px[b][i0 + ov] - jx;                          \
            const float dy = g_py[b][i0 + ov] - jy;                          \
            const float dz = g_pz[b][i0 + ov] - jz;                          \
            float q = dx * dx; q = fmaf(dy, dy, q); q = fmaf(dz, dz, q);     \
            const float t = fmaxf(r_minus(sqrt_approx(q), R), 0.0f);         \
            A1 = fmaf(t, t, A1);                                             \
        }                                                                    \
    }

    // Own cell: all ordered pairs incl. self (weight 1; self -> exact R^2).
    PAIR_BODY(own0, own1, i0, i0 + cnt)

    // Forward runs (each unordered cross pair once; weight 2).
#pragma unroll
    for (int r = 0; r < 5; r++) {
        const int rs0 = __shfl_sync(0xFFFFFFFFu, s0, r);
        const int rs1 = __shfl_sync(0xFFFFFFFFu, s1, r);
        PAIR_BODY(fwd0, fwd1, rs0, rs1)
    }
#undef PAIR_BODY

    float acc = (own0 + own1) + 2.0f * (fwd0 + fwd1);
#pragma unroll
    for (int off = 16; off > 0; off >>= 1)
        acc += __shfl_xor_sync(0xFFFFFFFFu, acc, off);

    if (lane == 0) sred[wid] = acc;
    __syncthreads();
    if (tid == 0) {
        float v = 0.0f;
#pragma unroll
        for (int w = 0; w < 8; w++) v += sred[w];
        g_part[blockIdx.x] = v;
        __threadfence();
        is_last = (atomicAdd(&g_tick4, 1u) == B4 - 1u);
        if (is_last) g_tick4 = 0;
    }
    __syncthreads();

    if (is_last) {
        __threadfence();
        const volatile float* gp = g_part;
        sred[tid] = (tid < B4) ? gp[tid] : 0.0f;
        __syncthreads();
#pragma unroll
        for (int s = T256 / 2; s > 0; s >>= 1) {
            if (tid < s) sred[tid] += sred[tid + s];
            __syncthreads();
        }
        if (tid == 0) {
            const float diag = (float)(NBATCH * NPTS) * (RADIUS * RADIUS);
            out[0] = (sred[0] - diag) /
                     ((float)NBATCH * (float)NPTS * (float)NPTS);
        }
    }
}

extern "C" void kernel_launch(void* const* d_in, const int* in_sizes, int n_in,
                              void* d_out, int out_size) {
    const float* xyz = (const float*)d_in[0];
    float* out = (float*)d_out;
    (void)in_sizes; (void)n_in; (void)out_size;

    k1_count  <<<B1, T256>>>(xyz);
    k2_scan   <<<B2, T256>>>();
    k3_scatter<<<B1, T256>>>(xyz);
    k4_main   <<<B4, T256>>>(out);
}

// round 16
// speedup vs baseline: 1.7860x; 1.0050x over previous
#include <cuda_runtime.h>
#include <cuda_bf16.h>

// CollisionRegularizer: mean over (B,N,N) of relu(R - dist)^2, diagonal masked.
// B=2, N=8192, xyz float32 (B,N,3). Output: 1 float (the mean).
//
// R11 vs R10 (25.7us; K4=13.1us @ occ 20%/250 blocks, prep=12.6us):
//  - K4 decomposed warp-per-(cell,run): 2000 cells x 6 runs = 12000 warp
//    tasks -> 1500 blocks (~10/SM). Kills grid starvation + run imbalance.
//  - Prep (K1/K2/K3) unchanged (deterministic binning, proven).
// Determinism: atomics only on integer tickets; all float sums fixed-order;
// scatter positions are pure functions of the input.

#define RADIUS  0.1f
#define NPTS    8192
#define NBATCH  2
#define GRES    10
#define NCELLS  (GRES * GRES * GRES)          // 1000
#define NCELLT  (NBATCH * NCELLS)             // 2000
#define NSEGB   (NPTS / 32)                   // 256 warp-segments per batch
#define NSEGT   (NBATCH * NSEGB)              // 512
#define CAP     64                            // staged own-points per warp

#define T256    256
#define B1      (NSEGT / 8)                   // 64 blocks
#define B2      (NCELLT / 8)                  // 250 blocks
#define NRUNS   6                             // own + 5 forward x-runs
#define NTASK   (NCELLT * NRUNS)              // 12000 warp tasks
#define B4      (NTASK / 8)                   // 1500 blocks

__device__ unsigned char  g_segcnt[NBATCH][NCELLS][NSEGB];
__device__ unsigned short g_segoff[NBATCH][NCELLS][NSEGB];
__device__ int   g_ctot[NBATCH][NCELLS];
__device__ int   g_start[NBATCH][NCELLS + 1];
__device__ float g_px[NBATCH][NPTS];
__device__ float g_py[NBATCH][NPTS];
__device__ float g_pz[NBATCH][NPTS];
__device__ float g_part[B4];
__device__ unsigned int g_tick2 = 0;
__device__ unsigned int g_tick4 = 0;

__device__ __forceinline__ float sqrt_approx(float x) {
    float r; asm("sqrt.approx.f32 %0, %1;" : "=f"(r) : "f"(x)); return r;
}
__device__ __forceinline__ float r_minus(float d, float R) {
    float r; asm("fma.rn.f32 %0, %1, 0fBF800000, %2;" : "=f"(r) : "f"(d), "f"(R)); return r;
}
__device__ __forceinline__ int point_cell(const float* __restrict__ p,
                                          float& x, float& y, float& z) {
    x = p[0]; y = p[1]; z = p[2];
    const int cx = min((int)(x * (float)GRES), GRES - 1);
    const int cy = min((int)(y * (float)GRES), GRES - 1);
    const int cz = min((int)(z * (float)GRES), GRES - 1);
    return cx + GRES * cy + GRES * GRES * cz;
}

// ---- K1: per-warp-segment cell counts (order-independent) ---------------
__global__ __launch_bounds__(T256)
void k1_count(const float* __restrict__ xyz) {
    const int lane = threadIdx.x & 31;
    const int gw   = blockIdx.x * 8 + (threadIdx.x >> 5);
    const int b  = gw / NSEGB;
    const int sg = gw % NSEGB;
    const int n  = sg * 32 + lane;
    float x, y, z;
    const int c = point_cell(xyz + ((size_t)b * NPTS + n) * 3, x, y, z);
    const unsigned int match = __match_any_sync(0xFFFFFFFFu, c);
    if (lane == (__ffs(match) - 1))
        g_segcnt[b][c][sg] = (unsigned char)__popc(match);
}

// ---- K2: per-cell segment scan (uchar4) + last-block cell scan ----------
__global__ __launch_bounds__(T256)
void k2_scan() {
    __shared__ int  swarp[8];
    __shared__ bool is_last;
    const int tid  = threadIdx.x;
    const int lane = tid & 31;
    const int wid  = tid >> 5;
    const int gw   = blockIdx.x * 8 + wid;    // 0..1999 == NCELLT

    {   // warp-per-cell: exclusive scan over 256 segment counts (as uchar4)
        const int b = gw / NCELLS, c = gw % NCELLS;
        uchar4*  cnt4 = reinterpret_cast<uchar4*>(&g_segcnt[b][c][0]);
        ushort4* off4 = reinterpret_cast<ushort4*>(&g_segoff[b][c][0]);
        int carry = 0;
#pragma unroll
        for (int ch = 0; ch < 2; ch++) {
            const int w = ch * 32 + lane;
            const uchar4 v = cnt4[w];
            cnt4[w] = make_uchar4(0, 0, 0, 0); // reset for next replay
            const int s = v.x + v.y + v.z + v.w;
            int incl = s;
#pragma unroll
            for (int o = 1; o < 32; o <<= 1) {
                const int t = __shfl_up_sync(0xFFFFFFFFu, incl, o);
                if (lane >= o) incl += t;
            }
            const int e = incl - s + carry;
            off4[w] = make_ushort4((unsigned short)e,
                                   (unsigned short)(e + v.x),
                                   (unsigned short)(e + v.x + v.y),
                                   (unsigned short)(e + v.x + v.y + v.z));
            carry += __shfl_sync(0xFFFFFFFFu, incl, 31);
        }
        if (lane == 0) g_ctot[b][c] = carry;
    }

    __syncthreads();
    if (tid == 0) {
        __threadfence();
        is_last = (atomicAdd(&g_tick2, 1u) == B2 - 1u);
        if (is_last) g_tick2 = 0;
    }
    __syncthreads();
    if (!is_last) return;
    __threadfence();

    for (int b = 0; b < NBATCH; b++) {        // 1000-cell exclusive scan
        const int i0 = tid * 4;
        int v0 = (i0 + 0 < NCELLS) ? g_ctot[b][i0 + 0] : 0;
        int v1 = (i0 + 1 < NCELLS) ? g_ctot[b][i0 + 1] : 0;
        int v2 = (i0 + 2 < NCELLS) ? g_ctot[b][i0 + 2] : 0;
        int v3 = (i0 + 3 < NCELLS) ? g_ctot[b][i0 + 3] : 0;
        const int s = v0 + v1 + v2 + v3;
        int incl = s;
#pragma unroll
        for (int o = 1; o < 32; o <<= 1) {
            const int t = __shfl_up_sync(0xFFFFFFFFu, incl, o);
            if (lane >= o) incl += t;
        }
        if (lane == 31) swarp[wid] = incl;
        __syncthreads();
        if (wid == 0 && lane < 8) {
            int wv = swarp[lane], wincl = wv;
#pragma unroll
            for (int o = 1; o < 8; o <<= 1) {
                const int t = __shfl_up_sync(0xFFu, wincl, o);
                if (lane >= o) wincl += t;
            }
            swarp[lane] = wincl - wv;
        }
        __syncthreads();
        const int excl = incl - s + swarp[wid];
        if (i0 + 0 < NCELLS) g_start[b][i0 + 0] = excl;
        if (i0 + 1 < NCELLS) g_start[b][i0 + 1] = excl + v0;
        if (i0 + 2 < NCELLS) g_start[b][i0 + 2] = excl + v0 + v1;
        if (i0 + 3 < NCELLS) g_start[b][i0 + 3] = excl + v0 + v1 + v2;
        if (i0 + 4 == NCELLS) g_start[b][NCELLS] = excl + s;
        __syncthreads();
    }
}

// ---- K3: deterministic scatter ------------------------------------------
__global__ __launch_bounds__(T256)
void k3_scatter(const float* __restrict__ xyz) {
    const int lane = threadIdx.x & 31;
    const int gw   = blockIdx.x * 8 + (threadIdx.x >> 5);
    const int b  = gw / NSEGB;
    const int sg = gw % NSEGB;
    const int n  = sg * 32 + lane;
    float x, y, z;
    const int c = point_cell(xyz + ((size_t)b * NPTS + n) * 3, x, y, z);
    const unsigned int match = __match_any_sync(0xFFFFFFFFu, c);
    const int rank = __popc(match & ((1u << lane) - 1u));
    const int pos  = g_start[b][c] + (int)g_segoff[b][c][sg] + rank;
    g_px[b][pos] = x;
    g_py[b][pos] = y;
    g_pz[b][pos] = z;
}

// ---- K4: warp-per-(cell,run) evaluation + fused final reduction ---------
__global__ __launch_bounds__(T256)
void k4_main(float* __restrict__ out) {
    __shared__ __align__(16) float wx[8][CAP];
    __shared__ __align__(16) float wy[8][CAP];
    __shared__ __align__(16) float wz[8][CAP];
    __shared__ float sred[T256];
    __shared__ bool  is_last;

    const int tid  = threadIdx.x;
    const int lane = tid & 31;
    const int wid  = tid >> 5;
    const int task = blockIdx.x * 8 + wid;    // 0..11999
    const int cell = task / NRUNS;
    const int run  = task % NRUNS;            // 0 = own, 1..5 = forward runs
    const int b = cell / NCELLS, c = cell % NCELLS;
    const int cx = c % GRES, cy = (c / GRES) % GRES, cz = c / (GRES * GRES);

    const int i0  = g_start[b][c];
    const int cnt = g_start[b][c + 1] - i0;
    const int scnt = min(cnt, CAP);

    for (int l = lane; l < scnt; l += 32) {
        wx[wid][l] = g_px[b][i0 + l];
        wy[wid][l] = g_py[b][i0 + l];
        wz[wid][l] = g_pz[b][i0 + l];
    }
    __syncwarp();

    // Run bounds (uniform across the warp).
    //  run 0: own cell [i0, i0+cnt)            weight 1 (self -> exact R^2)
    //  run 1..3: dz=+1, dy=run-2, x in [cx-1,cx+1]          weight 2
    //  run 4:    dz=0,  dy=+1,    x in [cx-1,cx+1]          weight 2
    //  run 5:    dz=0,  dy=0,     x = cx+1                  weight 2
    int rs0 = 0, rs1 = 0;
    float w = 2.0f;
    if (run == 0) {
        rs0 = i0; rs1 = i0 + cnt; w = 1.0f;
    } else {
        int dy, dz, x0, x1;
        if (run <= 3)      { dz = 1; dy = run - 2; x0 = max(cx - 1, 0); x1 = min(cx + 1, GRES - 1); }
        else if (run == 4) { dz = 0; dy = 1;       x0 = max(cx - 1, 0); x1 = min(cx + 1, GRES - 1); }
        else               { dz = 0; dy = 0;       x0 = cx + 1;         x1 = cx + 1; }
        const int ny = cy + dy, nz = cz + dz;
        if (ny >= 0 && ny < GRES && nz >= 0 && nz < GRES && x1 < GRES) {
            const int cb = GRES * ny + GRES * GRES * nz;
            rs0 = g_start[b][x0 + cb];
            rs1 = g_start[b][x1 + cb + 1];
        }
    }

    const float R = RADIUS;
    float acc0 = 0.0f, acc1 = 0.0f;
    for (int jj = rs0 + lane; jj < rs1; jj += 32) {
        const float jx = g_px[b][jj];
        const float jy = g_py[b][jj];
        const float jz = g_pz[b][jj];
        int ii = 0;
        for (; ii + 1 < scnt; ii += 2) {
            const float dx0 = wx[wid][ii]     - jx;
            const float dy0 = wy[wid][ii]     - jy;
            const float dz0 = wz[wid][ii]     - jz;
            const float dx1 = wx[wid][ii + 1] - jx;
            const float dy1 = wy[wid][ii + 1] - jy;
            const float dz1 = wz[wid][ii + 1] - jz;
            float q0 = dx0 * dx0; q0 = fmaf(dy0, dy0, q0); q0 = fmaf(dz0, dz0, q0);
            float q1 = dx1 * dx1; q1 = fmaf(dy1, dy1, q1); q1 = fmaf(dz1, dz1, q1);
            const float t0 = fmaxf(r_minus(sqrt_approx(q0), R), 0.0f);
            acc0 = fmaf(t0, t0, acc0);
            const float t1 = fmaxf(r_minus(sqrt_approx(q1), R), 0.0f);
            acc1 = fmaf(t1, t1, acc1);
        }
        if (ii < scnt) {
            const float dx = wx[wid][ii] - jx;
            const float dy = wy[wid][ii] - jy;
            const float dz = wz[wid][ii] - jz;
            float q = dx * dx; q = fmaf(dy, dy, q); q = fmaf(dz, dz, q);
            const float t = fmaxf(r_minus(sqrt_approx(q), R), 0.0f);
            acc0 = fmaf(t, t, acc0);
        }
        for (int ov = CAP; ov < cnt; ov++) {   // exact, astronomically rare
            const float dx = g_px[b][i0 + ov] - jx;
            const float dy = g_py[b][i0 + ov] - jy;
            const float dz = g_pz[b][i0 + ov] - jz;
            float q = dx * dx; q = fmaf(dy, dy, q); q = fmaf(dz, dz, q);
            const float t = fmaxf(r_minus(sqrt_approx(q), R), 0.0f);
            acc1 = fmaf(t, t, acc1);
        }
    }

    float acc = w * (acc0 + acc1);
#pragma unroll
    for (int off = 16; off > 0; off >>= 1)
        acc += __shfl_xor_sync(0xFFFFFFFFu, acc, off);

    if (lane == 0) sred[wid] = acc;
    __syncthreads();
    if (tid == 0) {
        float v = 0.0f;
#pragma unroll
        for (int wdx = 0; wdx < 8; wdx++) v += sred[wdx];   // fixed order
        g_part[blockIdx.x] = v;
        __threadfence();
        is_last = (atomicAdd(&g_tick4, 1u) == B4 - 1u);
        if (is_last) g_tick4 = 0;
    }
    __syncthreads();

    if (is_last) {
        __threadfence();
        const volatile float* gp = g_part;
        float v = 0.0f;
        for (int i = tid; i < B4; i += T256) v += gp[i];    // fixed order
        sred[tid] = v;
        __syncthreads();
#pragma unroll
        for (int s = T256 / 2; s > 0; s >>= 1) {
            if (tid < s) sred[tid] += sred[tid + s];
            __syncthreads();
        }
        if (tid == 0) {
            const float diag = (float)(NBATCH * NPTS) * (RADIUS * RADIUS);
            out[0] = (sred[0] - diag) /
                     ((float)NBATCH * (float)NPTS * (float)NPTS);
        }
    }
}

extern "C" void kernel_launch(void* const* d_in, const int* in_sizes, int n_in,
                              void* d_out, int out_size) {
    const float* xyz = (const float*)d_in[0];
    float* out = (float*)d_out;
    (void)in_sizes; (void)n_in; (void)out_size;

    k1_count  <<<B1, T256>>>(xyz);
    k2_scan   <<<B2, T256>>>();
    k3_scatter<<<B1, T256>>>(xyz);
    k4_main   <<<B4, T256>>>(out);
}

// round 17
// speedup vs baseline: 2.0241x; 1.1333x over previous
#include <cuda_runtime.h>
#include <cuda_bf16.h>

// CollisionRegularizer: mean over (B,N,N) of relu(R - dist)^2, diagonal masked.
// B=2, N=8192, xyz float32 (B,N,3). Output: 1 float (the mean).
//
// R12 vs R11 (25.6us; K4=14.3us):
//  - K4 inverted to thread-per-(point,run): 6 runs x 16384 sorted points =
//    98304 dense threads. Run-major layout -> warp = 32 consecutive sorted
//    positions -> warp-uniform run bounds + broadcast j-loads. No smem
//    staging, no lane-strided gaps, no CAP/overflow path.
//  - Sorted points packed float4 -> one LDG.128 per candidate j.
// Determinism: atomics only on integer tickets; all float sums fixed-order;
// scatter positions are pure functions of the input.

#define RADIUS  0.1f
#define NPTS    8192
#define NBATCH  2
#define GRES    10
#define NCELLS  (GRES * GRES * GRES)          // 1000
#define NCELLT  (NBATCH * NCELLS)             // 2000
#define NSEGB   (NPTS / 32)                   // 256 warp-segments per batch
#define NSEGT   (NBATCH * NSEGB)              // 512

#define T256    256
#define B1      (NSEGT / 8)                   // 64 blocks
#define B2      (NCELLT / 8)                  // 250 blocks
#define NRUNS   6                             // own + 5 forward x-runs
#define NTASK   (NRUNS * NBATCH * NPTS)       // 98304
#define B4      (NTASK / T256)                // 384 blocks

__device__ unsigned char  g_segcnt[NBATCH][NCELLS][NSEGB];
__device__ unsigned short g_segoff[NBATCH][NCELLS][NSEGB];
__device__ int    g_ctot[NBATCH][NCELLS];
__device__ int    g_start[NBATCH][NCELLS + 1];
__device__ float4 g_pts[NBATCH][NPTS];        // sorted (x,y,z,0)
__device__ float  g_part[B4];
__device__ unsigned int g_tick2 = 0;
__device__ unsigned int g_tick4 = 0;

__device__ __forceinline__ float sqrt_approx(float x) {
    float r; asm("sqrt.approx.f32 %0, %1;" : "=f"(r) : "f"(x)); return r;
}
__device__ __forceinline__ float r_minus(float d, float R) {
    float r; asm("fma.rn.f32 %0, %1, 0fBF800000, %2;" : "=f"(r) : "f"(d), "f"(R)); return r;
}
__device__ __forceinline__ int point_cell(float x, float y, float z,
                                          int& cx, int& cy, int& cz) {
    cx = min((int)(x * (float)GRES), GRES - 1);
    cy = min((int)(y * (float)GRES), GRES - 1);
    cz = min((int)(z * (float)GRES), GRES - 1);
    return cx + GRES * cy + GRES * GRES * cz;
}

// ---- K1: per-warp-segment cell counts (order-independent) ---------------
__global__ __launch_bounds__(T256)
void k1_count(const float* __restrict__ xyz) {
    const int lane = threadIdx.x & 31;
    const int gw   = blockIdx.x * 8 + (threadIdx.x >> 5);
    const int b  = gw / NSEGB;
    const int sg = gw % NSEGB;
    const int n  = sg * 32 + lane;
    const float* p = xyz + ((size_t)b * NPTS + n) * 3;
    int cx, cy, cz;
    const int c = point_cell(p[0], p[1], p[2], cx, cy, cz);
    const unsigned int match = __match_any_sync(0xFFFFFFFFu, c);
    if (lane == (__ffs(match) - 1))
        g_segcnt[b][c][sg] = (unsigned char)__popc(match);
}

// ---- K2: per-cell segment scan (uchar4) + last-block cell scan ----------
__global__ __launch_bounds__(T256)
void k2_scan() {
    __shared__ int  swarp[8];
    __shared__ bool is_last;
    const int tid  = threadIdx.x;
    const int lane = tid & 31;
    const int wid  = tid >> 5;
    const int gw   = blockIdx.x * 8 + wid;    // 0..1999 == NCELLT

    {   // warp-per-cell exclusive scan over 256 segment counts (uchar4)
        const int b = gw / NCELLS, c = gw % NCELLS;
        uchar4*  cnt4 = reinterpret_cast<uchar4*>(&g_segcnt[b][c][0]);
        ushort4* off4 = reinterpret_cast<ushort4*>(&g_segoff[b][c][0]);
        int carry = 0;
#pragma unroll
        for (int ch = 0; ch < 2; ch++) {
            const int w = ch * 32 + lane;
            const uchar4 v = cnt4[w];
            cnt4[w] = make_uchar4(0, 0, 0, 0); // reset for next replay
            const int s = v.x + v.y + v.z + v.w;
            int incl = s;
#pragma unroll
            for (int o = 1; o < 32; o <<= 1) {
                const int t = __shfl_up_sync(0xFFFFFFFFu, incl, o);
                if (lane >= o) incl += t;
            }
            const int e = incl - s + carry;
            off4[w] = make_ushort4((unsigned short)e,
                                   (unsigned short)(e + v.x),
                                   (unsigned short)(e + v.x + v.y),
                                   (unsigned short)(e + v.x + v.y + v.z));
            carry += __shfl_sync(0xFFFFFFFFu, incl, 31);
        }
        if (lane == 0) g_ctot[b][c] = carry;
    }

    __syncthreads();
    if (tid == 0) {
        __threadfence();
        is_last = (atomicAdd(&g_tick2, 1u) == B2 - 1u);
        if (is_last) g_tick2 = 0;
    }
    __syncthreads();
    if (!is_last) return;
    __threadfence();

    for (int b = 0; b < NBATCH; b++) {        // 1000-cell exclusive scan
        const int i0 = tid * 4;
        int v0 = (i0 + 0 < NCELLS) ? g_ctot[b][i0 + 0] : 0;
        int v1 = (i0 + 1 < NCELLS) ? g_ctot[b][i0 + 1] : 0;
        int v2 = (i0 + 2 < NCELLS) ? g_ctot[b][i0 + 2] : 0;
        int v3 = (i0 + 3 < NCELLS) ? g_ctot[b][i0 + 3] : 0;
        const int s = v0 + v1 + v2 + v3;
        int incl = s;
#pragma unroll
        for (int o = 1; o < 32; o <<= 1) {
            const int t = __shfl_up_sync(0xFFFFFFFFu, incl, o);
            if (lane >= o) incl += t;
        }
        if (lane == 31) swarp[wid] = incl;
        __syncthreads();
        if (wid == 0 && lane < 8) {
            int wv = swarp[lane], wincl = wv;
#pragma unroll
            for (int o = 1; o < 8; o <<= 1) {
                const int t = __shfl_up_sync(0xFFu, wincl, o);
                if (lane >= o) wincl += t;
            }
            swarp[lane] = wincl - wv;
        }
        __syncthreads();
        const int excl = incl - s + swarp[wid];
        if (i0 + 0 < NCELLS) g_start[b][i0 + 0] = excl;
        if (i0 + 1 < NCELLS) g_start[b][i0 + 1] = excl + v0;
        if (i0 + 2 < NCELLS) g_start[b][i0 + 2] = excl + v0 + v1;
        if (i0 + 3 < NCELLS) g_start[b][i0 + 3] = excl + v0 + v1 + v2;
        if (i0 + 4 == NCELLS) g_start[b][NCELLS] = excl + s;
        __syncthreads();
    }
}

// ---- K3: deterministic scatter into float4 ------------------------------
__global__ __launch_bounds__(T256)
void k3_scatter(const float* __restrict__ xyz) {
    const int lane = threadIdx.x & 31;
    const int gw   = blockIdx.x * 8 + (threadIdx.x >> 5);
    const int b  = gw / NSEGB;
    const int sg = gw % NSEGB;
    const int n  = sg * 32 + lane;
    const float* p = xyz + ((size_t)b * NPTS + n) * 3;
    const float x = p[0], y = p[1], z = p[2];
    int cx, cy, cz;
    const int c = point_cell(x, y, z, cx, cy, cz);
    const unsigned int match = __match_any_sync(0xFFFFFFFFu, c);
    const int rank = __popc(match & ((1u << lane) - 1u));
    const int pos  = g_start[b][c] + (int)g_segoff[b][c][sg] + rank;
    g_pts[b][pos] = make_float4(x, y, z, 0.0f);
}

// ---- K4: thread-per-(point,run), dense; fused final reduction -----------
__global__ __launch_bounds__(T256)
void k4_main(float* __restrict__ out) {
    __shared__ float sred[T256 / 32];
    __shared__ bool  is_last;

    const int tid  = threadIdx.x;
    const int lane = tid & 31;
    const int wid  = tid >> 5;

    // Run-major task layout: warp = 32 consecutive sorted positions.
    const int task = blockIdx.x * T256 + tid;     // 0..98303
    const int run  = task / (NBATCH * NPTS);      // 0 = own, 1..5 forward
    const int rem  = task - run * (NBATCH * NPTS);
    const int b    = rem / NPTS;
    const int pos  = rem % NPTS;

    const float4 pi = g_pts[b][pos];
    int cx, cy, cz;
    const int c = point_cell(pi.x, pi.y, pi.z, cx, cy, cz);

    // Run bounds (uniform across same-cell lanes).
    //  run 0: own cell (weight 1; self-pair -> exact R^2)
    //  run 1..3: dz=+1, dy=run-2, x in [cx-1,cx+1]   (weight 2)
    //  run 4:    dz=0,  dy=+1,    x in [cx-1,cx+1]   (weight 2)
    //  run 5:    dz=0,  dy=0,     x = cx+1           (weight 2)
    int rs0 = 0, rs1 = 0;
    float w = 2.0f;
    if (run == 0) {
        rs0 = g_start[b][c]; rs1 = g_start[b][c + 1]; w = 1.0f;
    } else {
        int dy, dz, x0, x1;
        if (run <= 3)      { dz = 1; dy = run - 2; x0 = max(cx - 1, 0); x1 = min(cx + 1, GRES - 1); }
        else if (run == 4) { dz = 0; dy = 1;       x0 = max(cx - 1, 0); x1 = min(cx + 1, GRES - 1); }
        else               { dz = 0; dy = 0;       x0 = cx + 1;         x1 = cx + 1; }
        const int ny = cy + dy, nz = cz + dz;
        if (ny >= 0 && ny < GRES && nz >= 0 && nz < GRES && x1 < GRES) {
            const int cb = GRES * ny + GRES * GRES * nz;
            rs0 = g_start[b][x0 + cb];
            rs1 = g_start[b][x1 + cb + 1];
        }
    }

    const float R = RADIUS;
    const float4* __restrict__ pts = g_pts[b];
    float acc0 = 0.0f, acc1 = 0.0f;
    int jj = rs0;
    for (; jj + 1 < rs1; jj += 2) {
        const float4 q0 = pts[jj];
        const float4 q1 = pts[jj + 1];
        const float dx0 = pi.x - q0.x, dy0 = pi.y - q0.y, dz0 = pi.z - q0.z;
        const float dx1 = pi.x - q1.x, dy1 = pi.y - q1.y, dz1 = pi.z - q1.z;
        float s0 = dx0 * dx0; s0 = fmaf(dy0, dy0, s0); s0 = fmaf(dz0, dz0, s0);
        float s1 = dx1 * dx1; s1 = fmaf(dy1, dy1, s1); s1 = fmaf(dz1, dz1, s1);
        const float t0 = fmaxf(r_minus(sqrt_approx(s0), R), 0.0f);
        acc0 = fmaf(t0, t0, acc0);
        const float t1 = fmaxf(r_minus(sqrt_approx(s1), R), 0.0f);
        acc1 = fmaf(t1, t1, acc1);
    }
    if (jj < rs1) {
        const float4 q = pts[jj];
        const float dx = pi.x - q.x, dy = pi.y - q.y, dz = pi.z - q.z;
        float s = dx * dx; s = fmaf(dy, dy, s); s = fmaf(dz, dz, s);
        const float t = fmaxf(r_minus(sqrt_approx(s), R), 0.0f);
        acc0 = fmaf(t, t, acc0);
    }

    float acc = w * (acc0 + acc1);
#pragma unroll
    for (int off = 16; off > 0; off >>= 1)        // deterministic bfly
        acc += __shfl_xor_sync(0xFFFFFFFFu, acc, off);

    if (lane == 0) sred[wid] = acc;
    __syncthreads();
    if (tid == 0) {
        float v = 0.0f;
#pragma unroll
        for (int wdx = 0; wdx < T256 / 32; wdx++) v += sred[wdx];  // fixed order
        g_part[blockIdx.x] = v;
        __threadfence();
        is_last = (atomicAdd(&g_tick4, 1u) == B4 - 1u);
        if (is_last) g_tick4 = 0;
    }
    __syncthreads();

    if (is_last) {
        __threadfence();
        const volatile float* gp = g_part;
        __shared__ float fin[T256];
        float v = 0.0f;
        for (int i = tid; i < B4; i += T256) v += gp[i];           // fixed order
        fin[tid] = v;
        __syncthreads();
#pragma unroll
        for (int s = T256 / 2; s > 0; s >>= 1) {
            if (tid < s) fin[tid] += fin[tid + s];
            __syncthreads();
        }
        if (tid == 0) {
            const float diag = (float)(NBATCH * NPTS) * (RADIUS * RADIUS);
            out[0] = (fin[0] - diag) /
                     ((float)NBATCH * (float)NPTS * (float)NPTS);
        }
    }
}

extern "C" void kernel_launch(void* const* d_in, const int* in_sizes, int n_in,
                              void* d_out, int out_size) {
    const float* xyz = (const float*)d_in[0];
    float* out = (float*)d_out;
    (void)in_sizes; (void)n_in; (void)out_size;

    k1_count  <<<B1, T256>>>(xyz);
    k2_scan   <<<B2, T256>>>();
    k3_scatter<<<B1, T256>>>(xyz);
    k4_main   <<<B4, T256>>>(out);
}